// round 12
// baseline (speedup 1.0000x reference)
#include <cuda_runtime.h>

#define Z0f 10.0f
#define EPSf 1e-6f
#define AP_R2 400.0f   // (DIAMETER*0.5)^2

// One ray: inputs (px..vz), writes 6 floats into o[0..5].
__device__ __forceinline__ void trace_ray(float px, float py, float pz,
                                          float vx, float vy, float vz,
                                          float R0, float Cx, float invR,
                                          float eta, float eta2,
                                          float* o)
{
    // sphere intersection: t^2 + b t + c = 0  (|V| = 1)
    float pcx = px - Cx, pcy = py, pcz = pz;
    float b = 2.0f * (vx*pcx + vy*pcy + vz*pcz);
    float c = pcx*pcx + pcy*pcy + pcz*pcz - R0*R0;
    float disc = b*b - 4.0f*c;
    float sd = sqrtf(fmaxf(disc, 0.0f));
    float t1 = (-b - sd) * 0.5f;
    float t2 = (-b + sd) * 0.5f;
    float t  = (t1 > EPSf) ? t1 : t2;
    bool hit = (disc >= 0.0f) && (t > EPSf);

    // collision point + aperture clip
    float qx = px + t*vx, qy = py + t*vy, qz = pz + t*vz;
    float r2 = qy*qy + qz*qz;
    hit = hit && (r2 <= AP_R2);

    // surface normal oriented against the ray
    float nx = (qx - Cx) * invR, ny = qy * invR, nz = qz * invR;
    float ndotv = nx*vx + ny*vy + nz*vz;
    if (ndotv > 0.0f) { nx = -nx; ny = -ny; nz = -nz; }

    // Snell refraction (vector form)
    float cosi  = -(nx*vx + ny*vy + nz*vz);
    float sin2t = eta2 * (1.0f - cosi*cosi);
    bool refract_ok = (sin2t <= 1.0f);
    float cost = sqrtf(fmaxf(1.0f - sin2t, 0.0f));
    float k = eta*cosi - cost;

    bool valid = hit && refract_ok;
    o[0] = valid ? qx : 0.0f;
    o[1] = valid ? qy : 0.0f;
    o[2] = valid ? qz : 0.0f;
    o[3] = valid ? (eta*vx + k*nx) : 0.0f;
    o[4] = valid ? (eta*vy + k*ny) : 0.0f;
    o[5] = valid ? (eta*vz + k*nz) : 0.0f;
}

// Process one pair-tile (lane s of the pair): select 2 rays from
// A,B,C (+exchanged x0,x1), trace, store 3 aligned float4.
__device__ __forceinline__ void process_tile(float4 A, float4 B, float4 C,
                                             float x0, float x1, int s, long p,
                                             float R0, float Cx, float invR,
                                             float eta, float eta2,
                                             float4* __restrict__ out4)
{
    float pax, pay, paz, pbx, pby, pbz;
    float vax, vay, vaz, vbx, vby, vbz;
    if (s == 0) {
        pax = A.x; pay = A.y; paz = A.z;
        pbx = A.w; pby = B.x; pbz = B.y;
        vax = C.x; vay = C.y; vaz = C.z;
        vbx = C.w; vby = x0;  vbz = x1;
    } else {
        pax = x0;  pay = x1;  paz = A.x;
        pbx = A.y; pby = A.z; pbz = A.w;
        vax = B.z; vay = B.w; vaz = C.x;
        vbx = C.y; vby = C.z; vbz = C.w;
    }

    float of[12];
    trace_ray(pax, pay, paz, vax, vay, vaz, R0, Cx, invR, eta, eta2, of);
    trace_ray(pbx, pby, pbz, vbx, vby, vbz, R0, Cx, invR, eta, eta2, of + 6);

    const long obase = 6L * p + 3 * s;
    __stcs(&out4[obase + 0], make_float4(of[0], of[1], of[2],  of[3]));
    __stcs(&out4[obase + 1], make_float4(of[4], of[5], of[6],  of[7]));
    __stcs(&out4[obase + 2], make_float4(of[8], of[9], of[10], of[11]));
}

// Software-pipelined: each thread handles pair-tiles q and q+H (two
// contiguous halves of the pair range -> all traffic stays coalesced).
// 6 front-batched LDG.128 per thread; tile-0 compute/stores overlap
// tile-1 load latency. Balanced even/odd load split, 4 shfl/tile.
__global__ __launch_bounds__(256, 6)
void refract_pipe2_kernel(const float4* __restrict__ P4,
                          const float4* __restrict__ V4,
                          const float* __restrict__ Rp,
                          const float* __restrict__ n1p,
                          const float* __restrict__ n2p,
                          float4* __restrict__ out4,
                          long H)     // half-range in pair units
{
    const long t = (long)blockIdx.x * blockDim.x + threadIdx.x;
    const int  s = (int)(t & 1);
    const long q0 = t >> 1;          // first tile
    const long q1 = q0 + H;          // second tile
    const long i0 = 3L * q0;
    const long i1 = 3L * q1;

    const float R0   = Rp[0];
    const float eta  = n1p[0] / n2p[0];
    const float Cx   = Z0f + R0;
    const float invR = 1.0f / R0;
    const float eta2 = eta * eta;

    // Front-batched loads: 6 LDG.128, balanced per lane.
    // even: A=P0, B=P1, C=V0    odd: A=P2, B=V1, C=V2
    float4 A0, B0, C0, A1, B1, C1;
    if (s == 0) {
        A0 = __ldcs(&P4[i0 + 0]);  B0 = __ldcs(&P4[i0 + 1]);  C0 = __ldcs(&V4[i0 + 0]);
        A1 = __ldcs(&P4[i1 + 0]);  B1 = __ldcs(&P4[i1 + 1]);  C1 = __ldcs(&V4[i1 + 0]);
    } else {
        A0 = __ldcs(&P4[i0 + 2]);  B0 = __ldcs(&V4[i0 + 1]);  C0 = __ldcs(&V4[i0 + 2]);
        A1 = __ldcs(&P4[i1 + 2]);  B1 = __ldcs(&V4[i1 + 1]);  C1 = __ldcs(&V4[i1 + 2]);
    }

    // Tile 0: exchange + compute + store (overlaps tile-1 loads in flight)
    {
        float sendL = (s == 0) ? B0.z : B0.x;
        float sendH = (s == 0) ? B0.w : B0.y;
        float x0 = __shfl_xor_sync(0xffffffffu, sendL, 1);
        float x1 = __shfl_xor_sync(0xffffffffu, sendH, 1);
        process_tile(A0, B0, C0, x0, x1, s, q0, R0, Cx, invR, eta, eta2, out4);
    }

    // Tile 1
    {
        float sendL = (s == 0) ? B1.z : B1.x;
        float sendH = (s == 0) ? B1.w : B1.y;
        float x0 = __shfl_xor_sync(0xffffffffu, sendL, 1);
        float x1 = __shfl_xor_sync(0xffffffffu, sendH, 1);
        process_tile(A1, B1, C1, x0, x1, s, q1, R0, Cx, invR, eta, eta2, out4);
    }
}

// Scalar tail for leftover rays. Not hit for N = 8388608.
__global__ void refract_tail_kernel(const float* __restrict__ P,
                                    const float* __restrict__ V,
                                    const float* __restrict__ Rp,
                                    const float* __restrict__ n1p,
                                    const float* __restrict__ n2p,
                                    float* __restrict__ out,
                                    int start, int N)
{
    int n = start + blockIdx.x * blockDim.x + threadIdx.x;
    if (n >= N) return;

    const float R0   = Rp[0];
    const float eta  = n1p[0] / n2p[0];
    const float Cx   = Z0f + R0;
    const float invR = 1.0f / R0;

    float px = P[3*n+0], py = P[3*n+1], pz = P[3*n+2];
    float vx = V[3*n+0], vy = V[3*n+1], vz = V[3*n+2];

    float pcx = px - Cx, pcy = py, pcz = pz;
    float b = 2.0f * (vx*pcx + vy*pcy + vz*pcz);
    float c = pcx*pcx + pcy*pcy + pcz*pcz - R0*R0;
    float disc = b*b - 4.0f*c;
    float sd = sqrtf(fmaxf(disc, 0.0f));
    float t1 = (-b - sd) * 0.5f;
    float t2 = (-b + sd) * 0.5f;
    float t  = (t1 > EPSf) ? t1 : t2;
    bool hit = (disc >= 0.0f) && (t > EPSf);

    float qx = px + t*vx, qy = py + t*vy, qz = pz + t*vz;
    float r2 = qy*qy + qz*qz;
    hit = hit && (r2 <= AP_R2);

    float nx = (qx - Cx) * invR, ny = qy * invR, nz = qz * invR;
    float ndotv = nx*vx + ny*vy + nz*vz;
    if (ndotv > 0.0f) { nx = -nx; ny = -ny; nz = -nz; }

    float cosi  = -(nx*vx + ny*vy + nz*vz);
    float sin2t = eta*eta * (1.0f - cosi*cosi);
    bool refract_ok = (sin2t <= 1.0f);
    float cost = sqrtf(fmaxf(1.0f - sin2t, 0.0f));
    float k = eta*cosi - cost;

    bool valid = hit && refract_ok;
    out[6*n+0] = valid ? qx : 0.0f;
    out[6*n+1] = valid ? qy : 0.0f;
    out[6*n+2] = valid ? qz : 0.0f;
    out[6*n+3] = valid ? (eta*vx + k*nx) : 0.0f;
    out[6*n+4] = valid ? (eta*vy + k*ny) : 0.0f;
    out[6*n+5] = valid ? (eta*vz + k*nz) : 0.0f;
}

extern "C" void kernel_launch(void* const* d_in, const int* in_sizes, int n_in,
                              void* d_out, int out_size)
{
    const float* P  = (const float*)d_in[0];
    const float* V  = (const float*)d_in[1];
    const float* R  = (const float*)d_in[2];
    const float* n1 = (const float*)d_in[3];
    const float* n2 = (const float*)d_in[4];
    float* out = (float*)d_out;

    int N = in_sizes[0] / 3;            // rays
    // Each thread covers 4 rays: pair q (rays 4q..) and pair q+H.
    // threads_used = fullBlocks*256; pairs covered = [0, threads_used),
    // contiguous, with H = threads_used/2.
    long threadsWanted = (long)N / 4;
    long fullBlocks = threadsWanted / 256;
    long threads_used = fullBlocks * 256;
    long rays_main = threads_used * 4;

    if (fullBlocks > 0) {
        long H = threads_used / 2;
        refract_pipe2_kernel<<<(unsigned)fullBlocks, 256>>>(
            (const float4*)P, (const float4*)V, R, n1, n2, (float4*)out, H);
    }
    if (rays_main < N) {
        int rem = (int)(N - rays_main);
        refract_tail_kernel<<<(rem + 255) / 256, 256>>>(
            P, V, R, n1, n2, out, (int)rays_main, N);
    }
}

// round 14
// speedup vs baseline: 1.0950x; 1.0950x over previous
#include <cuda_runtime.h>

#define Z0f 10.0f
#define EPSf 1e-6f
#define AP_R2 400.0f   // (DIAMETER*0.5)^2

// One ray: inputs (px..vz), writes 6 floats into o[0..5].
__device__ __forceinline__ void trace_ray(float px, float py, float pz,
                                          float vx, float vy, float vz,
                                          float R0, float Cx, float invR,
                                          float eta, float eta2,
                                          float* o)
{
    // sphere intersection: t^2 + b t + c = 0  (|V| = 1)
    float pcx = px - Cx, pcy = py, pcz = pz;
    float b = 2.0f * (vx*pcx + vy*pcy + vz*pcz);
    float c = pcx*pcx + pcy*pcy + pcz*pcz - R0*R0;
    float disc = b*b - 4.0f*c;
    float sd = sqrtf(fmaxf(disc, 0.0f));
    float t1 = (-b - sd) * 0.5f;
    float t2 = (-b + sd) * 0.5f;
    float t  = (t1 > EPSf) ? t1 : t2;
    bool hit = (disc >= 0.0f) && (t > EPSf);

    // collision point + aperture clip
    float qx = px + t*vx, qy = py + t*vy, qz = pz + t*vz;
    float r2 = qy*qy + qz*qz;
    hit = hit && (r2 <= AP_R2);

    // surface normal oriented against the ray
    float nx = (qx - Cx) * invR, ny = qy * invR, nz = qz * invR;
    float ndotv = nx*vx + ny*vy + nz*vz;
    if (ndotv > 0.0f) { nx = -nx; ny = -ny; nz = -nz; }

    // Snell refraction (vector form)
    float cosi  = -(nx*vx + ny*vy + nz*vz);
    float sin2t = eta2 * (1.0f - cosi*cosi);
    bool refract_ok = (sin2t <= 1.0f);
    float cost = sqrtf(fmaxf(1.0f - sin2t, 0.0f));
    float k = eta*cosi - cost;

    bool valid = hit && refract_ok;
    o[0] = valid ? qx : 0.0f;
    o[1] = valid ? qy : 0.0f;
    o[2] = valid ? qz : 0.0f;
    o[3] = valid ? (eta*vx + k*nx) : 0.0f;
    o[4] = valid ? (eta*vy + k*ny) : 0.0f;
    o[5] = valid ? (eta*vz + k*nz) : 0.0f;
}

// 2 rays/thread; a thread-pair owns 4 rays = 3 float4 of P/V, 6 float4 out.
// Balanced: even lane loads P0,P1,V0; odd lane loads P2,V1,V2 (3 LDG.128 each).
// Exchange: P1.zw -> odd, V1.xy -> even (4 shfl.b32/thread). No smem/barriers.
// 512-thread blocks to halve block churn; 32-bit index math throughout.
__global__ __launch_bounds__(512, 4)
void refract_shfl4_kernel(const float4* __restrict__ P4,
                          const float4* __restrict__ V4,
                          const float* __restrict__ Rp,
                          const float* __restrict__ n1p,
                          const float* __restrict__ n2p,
                          float4* __restrict__ out4)
{
    const unsigned t = blockIdx.x * 512u + threadIdx.x;  // grid sized exactly
    const unsigned p = t >> 1;      // pair index: rays 4p..4p+3 (p < 2^21)
    const unsigned s = t & 1u;
    const unsigned i3 = 3u * p;

    // Uniform scalars first (L1-broadcast, off the critical path).
    const float R0   = Rp[0];
    const float eta  = n1p[0] / n2p[0];
    const float Cx   = Z0f + R0;
    const float invR = 1.0f / R0;
    const float eta2 = eta * eta;

    // Balanced loads: 3 LDG.128 per lane.
    // even: A=P0, B=P1, C=V0    odd: A=P2, B=V1, C=V2
    float4 A, B, C;
    if (s == 0u) {
        A = __ldcs(&P4[i3 + 0]);
        B = __ldcs(&P4[i3 + 1]);
        C = __ldcs(&V4[i3 + 0]);
    } else {
        A = __ldcs(&P4[i3 + 2]);
        B = __ldcs(&V4[i3 + 1]);
        C = __ldcs(&V4[i3 + 2]);
    }

    // Cross-lane exchange within the pair (4 shfl.b32):
    //   even sends B.z,B.w (= P1.zw) -> odd receives as x0,x1
    //   odd  sends B.x,B.y (= V1.xy) -> even receives as x0,x1
    float sendL = (s == 0u) ? B.z : B.x;
    float sendH = (s == 0u) ? B.w : B.y;
    float x0 = __shfl_xor_sync(0xffffffffu, sendL, 1);
    float x1 = __shfl_xor_sync(0xffffffffu, sendH, 1);

    // Ray selection:
    // even: rayA P = A.xyz            rayA V = C.xyz
    //       rayB P = (A.w, B.x, B.y)  rayB V = (C.w, x0, x1)   [x=V1.xy]
    // odd : rayA P = (x0, x1, A.x)    rayA V = (B.z, B.w, C.x) [x=P1.zw]
    //       rayB P = A.yzw            rayB V = C.yzw
    float pax, pay, paz, pbx, pby, pbz;
    float vax, vay, vaz, vbx, vby, vbz;
    if (s == 0u) {
        pax = A.x; pay = A.y; paz = A.z;
        pbx = A.w; pby = B.x; pbz = B.y;
        vax = C.x; vay = C.y; vaz = C.z;
        vbx = C.w; vby = x0;  vbz = x1;
    } else {
        pax = x0;  pay = x1;  paz = A.x;
        pbx = A.y; pby = A.z; pbz = A.w;
        vax = B.z; vay = B.w; vaz = C.x;
        vbx = C.y; vby = C.z; vbz = C.w;
    }

    float of[12];
    trace_ray(pax, pay, paz, vax, vay, vaz, R0, Cx, invR, eta, eta2, of);
    trace_ray(pbx, pby, pbz, vbx, vby, vbz, R0, Cx, invR, eta, eta2, of + 6);

    // Store 3 aligned float4: even -> out4[6p+0..2], odd -> out4[6p+3..5]
    const unsigned obase = 6u * p + 3u * s;   // < 12.6M, fits u32
    __stcs(&out4[obase + 0], make_float4(of[0], of[1], of[2],  of[3]));
    __stcs(&out4[obase + 1], make_float4(of[4], of[5], of[6],  of[7]));
    __stcs(&out4[obase + 2], make_float4(of[8], of[9], of[10], of[11]));
}

// Scalar tail for leftover rays. Not hit for N = 8388608.
__global__ void refract_tail_kernel(const float* __restrict__ P,
                                    const float* __restrict__ V,
                                    const float* __restrict__ Rp,
                                    const float* __restrict__ n1p,
                                    const float* __restrict__ n2p,
                                    float* __restrict__ out,
                                    int start, int N)
{
    int n = start + blockIdx.x * blockDim.x + threadIdx.x;
    if (n >= N) return;

    const float R0   = Rp[0];
    const float eta  = n1p[0] / n2p[0];
    const float Cx   = Z0f + R0;
    const float invR = 1.0f / R0;

    float px = P[3*n+0], py = P[3*n+1], pz = P[3*n+2];
    float vx = V[3*n+0], vy = V[3*n+1], vz = V[3*n+2];

    float pcx = px - Cx, pcy = py, pcz = pz;
    float b = 2.0f * (vx*pcx + vy*pcy + vz*pcz);
    float c = pcx*pcx + pcy*pcy + pcz*pcz - R0*R0;
    float disc = b*b - 4.0f*c;
    float sd = sqrtf(fmaxf(disc, 0.0f));
    float t1 = (-b - sd) * 0.5f;
    float t2 = (-b + sd) * 0.5f;
    float t  = (t1 > EPSf) ? t1 : t2;
    bool hit = (disc >= 0.0f) && (t > EPSf);

    float qx = px + t*vx, qy = py + t*vy, qz = pz + t*vz;
    float r2 = qy*qy + qz*qz;
    hit = hit && (r2 <= AP_R2);

    float nx = (qx - Cx) * invR, ny = qy * invR, nz = qz * invR;
    float ndotv = nx*vx + ny*vy + nz*vz;
    if (ndotv > 0.0f) { nx = -nx; ny = -ny; nz = -nz; }

    float cosi  = -(nx*vx + ny*vy + nz*vz);
    float sin2t = eta*eta * (1.0f - cosi*cosi);
    bool refract_ok = (sin2t <= 1.0f);
    float cost = sqrtf(fmaxf(1.0f - sin2t, 0.0f));
    float k = eta*cosi - cost;

    bool valid = hit && refract_ok;
    out[6*n+0] = valid ? qx : 0.0f;
    out[6*n+1] = valid ? qy : 0.0f;
    out[6*n+2] = valid ? qz : 0.0f;
    out[6*n+3] = valid ? (eta*vx + k*nx) : 0.0f;
    out[6*n+4] = valid ? (eta*vy + k*ny) : 0.0f;
    out[6*n+5] = valid ? (eta*vz + k*nz) : 0.0f;
}

extern "C" void kernel_launch(void* const* d_in, const int* in_sizes, int n_in,
                              void* d_out, int out_size)
{
    const float* P  = (const float*)d_in[0];
    const float* V  = (const float*)d_in[1];
    const float* R  = (const float*)d_in[2];
    const float* n1 = (const float*)d_in[3];
    const float* n2 = (const float*)d_in[4];
    float* out = (float*)d_out;

    int N = in_sizes[0] / 3;            // rays
    // Full 512-thread blocks only (1024 rays per block) so warps are complete.
    long nGroups = (long)N / 4;         // thread pairs
    long threadsWanted = nGroups * 2;
    long fullBlocks = threadsWanted / 512;
    long rays_main = fullBlocks * 1024;

    if (fullBlocks > 0) {
        refract_shfl4_kernel<<<(unsigned)fullBlocks, 512>>>(
            (const float4*)P, (const float4*)V, R, n1, n2, (float4*)out);
    }
    if (rays_main < N) {
        int rem = (int)(N - rays_main);
        refract_tail_kernel<<<(rem + 255) / 256, 256>>>(
            P, V, R, n1, n2, out, (int)rays_main, N);
    }
}